// round 12
// baseline (speedup 1.0000x reference)
#include <cuda_runtime.h>

// ============================================================================
// EDF ensemble detection fusion, N = 8192.  R10: R7 passing architecture,
// with init+rank+gather fused into ONE single-block prep kernel using
// score-bucket + exact in-bucket stable rank (no grid sync needed).
//
// Launches:
//   K0 k_prep  : [1 block] histograms, scans, scatter, exact stable rank,
//                scratch reset   (replaces R7 k_init + k_rank + k_gather)
//   K1 k_edges : [R7 verbatim] warp-per-x-row exact IoU, pruned ranges
//   K2 k_post  : [R7 verbatim] CSR + greedy-cluster worklist fixpoint +
//                stats + first-pick + output
// ============================================================================

#define NN 8192
#define ECAP 60000
#define BINS 256
#define SBK 1024
#define INV_BINW (256.0f / 1920.0f)
#define W_IMG 1920.0f
#define H_IMG 1080.0f

__device__ unsigned long long g_bk[NN];   // bucket-ordered score keys
__device__ int    g_posx[NN];             // original i -> x-bin position
__device__ int    g_binOff[BINS + 1];
__device__ float  g_bx1[NN], g_by1[NN], g_bx2[NN], g_by2[NN], g_s[NN];
__device__ float4 g_xs4[NN];              // x-bin-ordered clipped boxes
__device__ int    g_xord[NN];             // x-bin position -> score rank
__device__ int    g_degIn[NN];
__device__ int    g_cursor[NN];
__device__ int    g_eh[ECAP], g_ej[ECAP], g_inList[ECAP];
__device__ int    g_ecnt;
__device__ int    g_actA[NN], g_actB[NN];
__device__ int    g_count[NN];
__device__ float  g_sum[NN];
__device__ unsigned g_maxY2[NN];
__device__ int    g_first[NN];

// ---------------------------------------------------------------------------
// K0: single-block prep.
//  pass1: score-bucket + x-bin histograms (smem atomics) + scratch reset
//  scans: 1024-bucket and 256-bin exclusive scans in smem
//  pass2: scatter score keys into bucket order; clipped float4 into x-bins
//  pass3: exact stable rank = bucketOff + count(key < mine within bucket);
//         write score-sorted SoA and xord mapping.
// Bucket function is monotone in the descending-score key u = ~bits(score)
// (floor of a monotone float map), and keys are unique via index low bits,
// so ranks are exactly the stable argsort(-scores) permutation.
// ---------------------------------------------------------------------------
__global__ void __launch_bounds__(1024)
k_prep(const float* __restrict__ boxes, const float* __restrict__ scores) {
    __shared__ int sHistS[SBK];        // later reused as scatter cursors
    __shared__ int sOffS[SBK + 1];
    __shared__ int sHistX[BINS];       // later reused as scatter cursors
    __shared__ int sOffX[BINS + 1];
    __shared__ int sTmp[BINS];
    int tid = threadIdx.x;

    sHistS[tid] = 0;
    if (tid < BINS) sHistX[tid] = 0;
    if (tid == 0) g_ecnt = 0;
    __syncthreads();

    const unsigned u0 = ~__float_as_uint(1.0f);
    const float sscale = (float)SBK /
                         (float)(~__float_as_uint(0.3f) - u0);

    // pass 1: histograms + scratch reset
    for (int i = tid; i < NN; i += 1024) {
        unsigned u = ~__float_as_uint(scores[i]);
        int d = (int)(u - u0);
        int sb = (d <= 0) ? 0 : min(SBK - 1, (int)((float)d * sscale));
        float x1 = fminf(fmaxf(boxes[i * 4 + 0], 0.0f), W_IMG);
        int xb = min((int)(x1 * INV_BINW), BINS - 1);
        atomicAdd(&sHistS[sb], 1);
        atomicAdd(&sHistX[xb], 1);
        g_degIn[i]  = 0;
        g_cursor[i] = 0;
        g_count[i]  = 0;
        g_sum[i]    = 0.0f;
        g_maxY2[i]  = 0u;              // y2 >= 0 -> 0-bits is a valid -inf
        g_first[i]  = NN;
    }
    __syncthreads();

    // scan S: 1024-entry Hillis-Steele, inclusive -> exclusive in place
    {
        int v = sHistS[tid];
        sOffS[tid] = v;
        __syncthreads();
        for (int o = 1; o < SBK; o <<= 1) {
            int t = (tid >= o) ? sOffS[tid - o] : 0;
            __syncthreads();
            sOffS[tid] += t;
            __syncthreads();
        }
        int incl = sOffS[tid];
        __syncthreads();
        sOffS[tid] = incl - v;                 // exclusive
        if (tid == SBK - 1) sOffS[SBK] = incl; // == NN
        sHistS[tid] = 0;                       // reuse as cursor
    }
    __syncthreads();

    // scan X: 256-entry (guarded full-block pattern)
    {
        if (tid < BINS) sTmp[tid] = sHistX[tid];
        __syncthreads();
        for (int o = 1; o < BINS; o <<= 1) {
            int t = (tid >= o && tid < BINS) ? sTmp[tid - o] : 0;
            __syncthreads();
            if (tid < BINS) sTmp[tid] += t;
            __syncthreads();
        }
        if (tid < BINS) {
            int ex = sTmp[tid] - sHistX[tid];
            sOffX[tid] = ex;
            g_binOff[tid] = ex;
            if (tid == BINS - 1) { sOffX[BINS] = sTmp[tid]; g_binOff[BINS] = sTmp[tid]; }
            sHistX[tid] = 0;                   // reuse as cursor
        }
    }
    __syncthreads();

    // pass 2: scatter keys + x-boxes
    for (int i = tid; i < NN; i += 1024) {
        unsigned u = ~__float_as_uint(scores[i]);
        int d = (int)(u - u0);
        int sb = (d <= 0) ? 0 : min(SBK - 1, (int)((float)d * sscale));
        int ps = sOffS[sb] + atomicAdd(&sHistS[sb], 1);
        g_bk[ps] = (((unsigned long long)u) << 32) | (unsigned)i;

        float x1 = fminf(fmaxf(boxes[i * 4 + 0], 0.0f), W_IMG);
        float y1 = fminf(fmaxf(boxes[i * 4 + 1], 0.0f), H_IMG);
        float x2 = fminf(fmaxf(boxes[i * 4 + 2], 0.0f), W_IMG);
        float y2 = fminf(fmaxf(boxes[i * 4 + 3], 0.0f), H_IMG);
        int xb = min((int)(x1 * INV_BINW), BINS - 1);
        int px = sOffX[xb] + atomicAdd(&sHistX[xb], 1);
        g_xs4[px] = make_float4(x1, y1, x2, y2);
        g_posx[i] = px;
    }
    __syncthreads();   // block-wide global store->load ordering (same block)

    // pass 3: exact stable rank -> score-sorted SoA
    for (int i = tid; i < NN; i += 1024) {
        unsigned u = ~__float_as_uint(scores[i]);
        int d = (int)(u - u0);
        int sb = (d <= 0) ? 0 : min(SBK - 1, (int)((float)d * sscale));
        unsigned long long my = (((unsigned long long)u) << 32) | (unsigned)i;
        int st = sOffS[sb], en = sOffS[sb + 1];
        int c = 0;
        for (int t = st; t < en; t++) c += (g_bk[t] < my) ? 1 : 0;
        int r = st + c;

        float x1 = fminf(fmaxf(boxes[i * 4 + 0], 0.0f), W_IMG);
        float y1 = fminf(fmaxf(boxes[i * 4 + 1], 0.0f), H_IMG);
        float x2 = fminf(fmaxf(boxes[i * 4 + 2], 0.0f), W_IMG);
        float y2 = fminf(fmaxf(boxes[i * 4 + 3], 0.0f), H_IMG);
        g_bx1[r] = x1; g_by1[r] = y1; g_bx2[r] = x2; g_by2[r] = y2;
        g_s[r] = scores[i];
        g_xord[g_posx[i]] = r;
    }
}

// ---------------------------------------------------------------------------
// K1: [R7 verbatim] warp per bin-sorted row a. Candidates: positions (a, end)
// where end = binOff[bin(x2_a + 2) + 1]; conservative superset, exact
// reference arithmetic decides. Edges in score-index space (i<j).
// ---------------------------------------------------------------------------
__global__ void k_edges() {
    int warp = (blockIdx.x * blockDim.x + threadIdx.x) >> 5;
    int lane = threadIdx.x & 31;
    if (warp >= NN) return;
    int a = warp;
    float4 A = g_xs4[a];
    int   pa = g_xord[a];
    float aa = __fmul_rn(__fadd_rn(__fsub_rn(A.z, A.x), 1.0f),
                         __fadd_rn(__fsub_rn(A.w, A.y), 1.0f));
    float thresh = A.z + 2.0f;
    int binMax = (int)(thresh * INV_BINW);
    if (binMax > BINS - 1) binMax = BINS - 1;
    int end = g_binOff[binMax + 1];

    for (int b0 = a + 1; b0 < end; b0 += 32) {
        int b = b0 + lane;
        if (b < end) {
            float4 B = g_xs4[b];
            if (B.x <= thresh) {
                float ix1 = fmaxf(A.x, B.x);
                float iy1 = fmaxf(A.y, B.y);
                float ix2 = fminf(A.z, B.z);
                float iy2 = fminf(A.w, B.w);
                float iw = fmaxf(__fadd_rn(__fsub_rn(ix2, ix1), 1.0f), 0.0f);
                float ih = fmaxf(__fadd_rn(__fsub_rn(iy2, iy1), 1.0f), 0.0f);
                float inter = __fmul_rn(iw, ih);
                if (inter > 0.0f) {
                    float ab = __fmul_rn(__fadd_rn(__fsub_rn(B.z, B.x), 1.0f),
                                         __fadd_rn(__fsub_rn(B.w, B.y), 1.0f));
                    float uni = __fsub_rn(__fadd_rn(aa, ab), inter);
                    if (__fdiv_rn(inter, uni) > 0.5f) {
                        int pb = g_xord[b];
                        int i = min(pa, pb);
                        int j = max(pa, pb);
                        int e = atomicAdd(&g_ecnt, 1);
                        if (e < ECAP) {
                            g_eh[e] = i;
                            g_ej[e] = j;
                            atomicAdd(&g_degIn[j], 1);
                        }
                    }
                }
            }
        }
    }
}

// ---------------------------------------------------------------------------
// K2: [R7 verbatim] fused single-block tail: CSR scan+fill, greedy-cluster
// worklist fixpoint (lexicographic-first MIS), stats, first-pick, output.
// ---------------------------------------------------------------------------
__global__ void k_post(const int* __restrict__ nmp, float* __restrict__ out,
                       int out_size) {
    __shared__ short          s_sc[NN];      // -1 undecided / cluster id
    __shared__ unsigned short s_off[NN];     // CSR starts (total < 65536)
    __shared__ int            s_sums[1024];
    __shared__ int            s_total, s_cnt;
    int tid = threadIdx.x;

    // (a) scan of g_degIn -> s_off (exclusive), s_total
    int base = tid * 8;
    int ex[8];
    int sum = 0;
#pragma unroll
    for (int r = 0; r < 8; r++) {
        int v = g_degIn[base + r];
        ex[r] = sum;
        sum += v;
    }
    s_sums[tid] = sum;
    __syncthreads();
    for (int off = 1; off < 1024; off <<= 1) {
        int t = (tid >= off) ? s_sums[tid - off] : 0;
        __syncthreads();
        s_sums[tid] += t;
        __syncthreads();
    }
    int blockEx = s_sums[tid] - sum;
#pragma unroll
    for (int r = 0; r < 8; r++)
        s_off[base + r] = (unsigned short)(blockEx + ex[r]);
    if (tid == 1023) s_total = blockEx + sum;
    if (tid == 0) s_cnt = 0;
    __syncthreads();
    int total = s_total;

    // (b) CSR fill
    {
        int ec = g_ecnt;
        if (ec > ECAP) ec = ECAP;
        for (int e = tid; e < ec; e += 1024) {
            int j = g_ej[e];
            int pos = (int)s_off[j] + atomicAdd(&g_cursor[j], 1);
            g_inList[pos] = g_eh[e];
        }
    }
    __syncthreads();

    // (c) init: deg-0 -> head; others -> worklist
    for (int i = tid; i < NN; i += 1024) {
        int st = s_off[i];
        int en = (i < NN - 1) ? (int)s_off[i + 1] : total;
        if (st == en) {
            s_sc[i] = (short)i;
        } else {
            s_sc[i] = -1;
            int p = atomicAdd(&s_cnt, 1);
            g_actA[p] = i;
        }
    }
    __syncthreads();
    int nact = s_cnt;
    int* cur = g_actA;
    int* nxt = g_actB;

    for (int round = 0; round < 2048 && nact > 0; round++) {
        if (tid == 0) s_cnt = 0;
        __syncthreads();
        for (int t = tid; t < nact; t += 1024) {
            int i = cur[t];
            int st = s_off[i];
            int en = (i < NN - 1) ? (int)s_off[i + 1] : total;
            int m = 0x7fffffff, u = 0x7fffffff;
            for (int p = st; p < en; p++) {
                int h = g_inList[p];
                int c = s_sc[h];
                if (c == h)      m = min(m, h);
                else if (c < 0)  u = min(u, h);
            }
            if (m < u)                 s_sc[i] = (short)m;
            else if (u == 0x7fffffff)  s_sc[i] = (short)i;
            else { int p = atomicAdd(&s_cnt, 1); nxt[p] = i; }
        }
        __syncthreads();
        nact = s_cnt;
        int* tmp = cur; cur = nxt; nxt = tmp;
        __syncthreads();
    }

    // (d) stats
    for (int j = tid; j < NN; j += 1024) {
        int c = s_sc[j];
        atomicAdd(&g_count[c], 1);
        atomicAdd(&g_sum[c], g_s[j]);
        atomicMax(&g_maxY2[c], __float_as_uint(g_by2[j]));  // y2>=0 monotone
    }
    __syncthreads();

    // (e) first pick
    for (int j = tid; j < NN; j += 1024) {
        int c = s_sc[j];
        if (g_by2[j] >= __uint_as_float(g_maxY2[c])) atomicMin(&g_first[c], j);
    }
    __syncthreads();

    // (f) output: out[0..5N) = (N,5) rows, out[5N..6N) = keep as 0/1 floats.
    //     valid: counts >= nm/3  <=>  3*count >= nm (exact in ints)
    int nm = nmp[0];
    if (nm < 1 || nm > 1000000) {
        float f = __int_as_float(nm);
        nm = (int)f;
        if (nm < 1) nm = 1;
    }
    for (int j = tid; j < NN; j += 1024) {
        int c = s_sc[j];
        bool keep = (j == g_first[c]) && (3 * g_count[c] >= nm);
        float r0 = 0.f, r1 = 0.f, r2 = 0.f, r3 = 0.f, r4 = 0.f, kf = 0.f;
        if (keep) {
            r0 = g_bx1[j]; r1 = g_by1[j]; r2 = g_bx2[j]; r3 = g_by2[j];
            r4 = __fdiv_rn(g_sum[c], (float)nm);
            kf = 1.0f;
        }
        long long obase = (long long)j * 5;
        if (obase + 4 < out_size) {
            out[obase + 0] = r0; out[obase + 1] = r1; out[obase + 2] = r2;
            out[obase + 3] = r3; out[obase + 4] = r4;
        }
        long long kpos = (long long)NN * 5 + j;
        if (kpos < out_size) out[kpos] = kf;
    }
}

// ---------------------------------------------------------------------------
extern "C" void kernel_launch(void* const* d_in, const int* in_sizes, int n_in,
                              void* d_out, int out_size) {
    const float* boxes  = nullptr;
    const float* scores = nullptr;
    const int*   nmp    = nullptr;
    for (int k = 0; k < n_in; k++) {
        if (in_sizes[k] == NN * 4)      boxes  = (const float*)d_in[k];
        else if (in_sizes[k] == NN)     scores = (const float*)d_in[k];
        else if (in_sizes[k] == 1)      nmp    = (const int*)d_in[k];
    }
    if (!boxes)  boxes  = (const float*)d_in[0];
    if (!scores) scores = (const float*)d_in[1];
    if (!nmp)    nmp    = (const int*)d_in[n_in - 1];

    k_prep<<<1, 1024>>>(boxes, scores);
    k_edges<<<NN / 8, 256>>>();            // 8192 warps, warp per x-row
    k_post<<<1, 1024>>>(nmp, (float*)d_out, out_size);
}

// round 15
// speedup vs baseline: 2.3670x; 2.3670x over previous
#include <cuda_runtime.h>

// ============================================================================
// EDF ensemble detection fusion, N = 8192.  R12:
//  - bucket-rank prep (proven in R10) executed MULTI-BLOCK across 4 kernels,
//    kernel boundaries provide the ordering (no grid barriers)
//  - k_edges: R7 verbatim (proven, 16.7 us)
//  - k_post: fixpoint with register-cached neighbor lists (rounds touch only
//    shared memory; global fallback for degree > 8)
//
// Launches:
//   K0 k_init    [32 blk] score-bucket + x-bin histograms, scratch reset
//   K1 k_scan    [1 blk]  scans both histograms; zero cursors/hist/ecnt
//   K2 k_scatter [32 blk] scatter score keys + clipped float4 boxes
//   K3 k_rankg   [32 blk] exact stable rank -> score SoA + xord
//   K4 k_edges   [1024 blk] warp-per-x-row exact IoU, pruned ranges
//   K5 k_post    [1 blk]  CSR + cached-neighbor fixpoint + stats + output
// ============================================================================

#define NN 8192
#define ECAP 60000
#define BINS 256
#define SBK 1024
#define INV_BINW (256.0f / 1920.0f)
#define W_IMG 1920.0f
#define H_IMG 1080.0f

__device__ int    g_histS[SBK], g_offS[SBK + 1], g_curS[SBK];
__device__ int    g_histX[BINS], g_offX[BINS + 1], g_curX[BINS];
__device__ unsigned long long g_bk[NN];   // bucket-ordered score keys
__device__ int    g_posx[NN];             // original i -> x-bin position
__device__ int    g_binOff[BINS + 1];
__device__ float  g_bx1[NN], g_by1[NN], g_bx2[NN], g_by2[NN], g_s[NN];
__device__ float4 g_xs4[NN];              // x-bin-ordered clipped boxes
__device__ int    g_xord[NN];             // x-bin position -> score rank
__device__ int    g_degIn[NN];
__device__ int    g_cursor[NN];
__device__ int    g_eh[ECAP], g_ej[ECAP], g_inList[ECAP];
__device__ int    g_ecnt;
__device__ int    g_count[NN];
__device__ float  g_sum[NN];
__device__ unsigned g_maxY2[NN];
__device__ int    g_first[NN];

// Score bucket: monotone map of u = ~bits(score) (descending-score order).
__device__ __forceinline__ int score_bucket(float s) {
    const unsigned u0 = ~__float_as_uint(1.0f);
    const float sscale = (float)SBK /
                         (float)(~__float_as_uint(0.3f) - u0);
    unsigned u = ~__float_as_uint(s);
    int d = (int)(u - u0);
    return (d <= 0) ? 0 : min(SBK - 1, (int)((float)d * sscale));
}

// ---------------------------------------------------------------------------
// K0: histograms (global atomics) + per-replay scratch reset.
// (Previous replay is fully complete: kernel order within the graph.)
// ---------------------------------------------------------------------------
__global__ void k_init(const float* __restrict__ boxes,
                       const float* __restrict__ scores) {
    int i = blockIdx.x * blockDim.x + threadIdx.x;
    if (i >= NN) return;
    int sb = score_bucket(scores[i]);
    float x1 = fminf(fmaxf(boxes[i * 4 + 0], 0.0f), W_IMG);
    int xb = min((int)(x1 * INV_BINW), BINS - 1);
    atomicAdd(&g_histS[sb], 1);
    atomicAdd(&g_histX[xb], 1);
    g_degIn[i]  = 0;
    g_cursor[i] = 0;
    g_count[i]  = 0;
    g_sum[i]    = 0.0f;
    g_maxY2[i]  = 0u;                  // y2 >= 0 -> 0-bits is a valid -inf
    g_first[i]  = NN;
}

// ---------------------------------------------------------------------------
// K1: single block scans both histograms -> offsets; zeroes hist (for next
// replay), cursors (for this replay's scatter) and ecnt.
// ---------------------------------------------------------------------------
__global__ void __launch_bounds__(1024)
k_scan() {
    __shared__ int sS[SBK];
    __shared__ int sX[BINS];
    int tid = threadIdx.x;

    int v = g_histS[tid];
    sS[tid] = v;
    __syncthreads();
    for (int o = 1; o < SBK; o <<= 1) {
        int t = (tid >= o) ? sS[tid - o] : 0;
        __syncthreads();
        sS[tid] += t;
        __syncthreads();
    }
    g_offS[tid] = sS[tid] - v;
    if (tid == SBK - 1) g_offS[SBK] = sS[tid];
    g_histS[tid] = 0;
    g_curS[tid]  = 0;

    int v2 = (tid < BINS) ? g_histX[tid] : 0;
    if (tid < BINS) sX[tid] = v2;
    __syncthreads();
    for (int o = 1; o < BINS; o <<= 1) {
        int t = (tid >= o && tid < BINS) ? sX[tid - o] : 0;
        __syncthreads();
        if (tid < BINS) sX[tid] += t;
        __syncthreads();
    }
    if (tid < BINS) {
        int ex = sX[tid] - v2;
        g_offX[tid] = ex;
        g_binOff[tid] = ex;
        if (tid == BINS - 1) { g_offX[BINS] = sX[tid]; g_binOff[BINS] = sX[tid]; }
        g_histX[tid] = 0;
        g_curX[tid]  = 0;
    }
    if (tid == 0) g_ecnt = 0;
}

// ---------------------------------------------------------------------------
// K2: scatter score keys into bucket order; clipped float4 boxes into x-bins.
// ---------------------------------------------------------------------------
__global__ void k_scatter(const float* __restrict__ boxes,
                          const float* __restrict__ scores) {
    int i = blockIdx.x * blockDim.x + threadIdx.x;
    if (i >= NN) return;
    unsigned u = ~__float_as_uint(scores[i]);
    int sb = score_bucket(scores[i]);
    int ps = g_offS[sb] + atomicAdd(&g_curS[sb], 1);
    g_bk[ps] = (((unsigned long long)u) << 32) | (unsigned)i;

    float x1 = fminf(fmaxf(boxes[i * 4 + 0], 0.0f), W_IMG);
    float y1 = fminf(fmaxf(boxes[i * 4 + 1], 0.0f), H_IMG);
    float x2 = fminf(fmaxf(boxes[i * 4 + 2], 0.0f), W_IMG);
    float y2 = fminf(fmaxf(boxes[i * 4 + 3], 0.0f), H_IMG);
    int xb = min((int)(x1 * INV_BINW), BINS - 1);
    int px = g_offX[xb] + atomicAdd(&g_curX[xb], 1);
    g_xs4[px] = make_float4(x1, y1, x2, y2);
    g_posx[i] = px;
}

// ---------------------------------------------------------------------------
// K3: exact stable rank (bucket offset + in-bucket count of smaller unique
// keys) -> identical permutation to stable argsort(-scores). Writes score-
// sorted SoA and xord mapping.
// ---------------------------------------------------------------------------
__global__ void k_rankg(const float* __restrict__ boxes,
                        const float* __restrict__ scores) {
    int i = blockIdx.x * blockDim.x + threadIdx.x;
    if (i >= NN) return;
    unsigned u = ~__float_as_uint(scores[i]);
    int sb = score_bucket(scores[i]);
    unsigned long long my = (((unsigned long long)u) << 32) | (unsigned)i;
    int st = g_offS[sb], en = g_offS[sb + 1];
    int c = 0;
    for (int t = st; t < en; t++) c += (g_bk[t] < my) ? 1 : 0;
    int r = st + c;

    float x1 = fminf(fmaxf(boxes[i * 4 + 0], 0.0f), W_IMG);
    float y1 = fminf(fmaxf(boxes[i * 4 + 1], 0.0f), H_IMG);
    float x2 = fminf(fmaxf(boxes[i * 4 + 2], 0.0f), W_IMG);
    float y2 = fminf(fmaxf(boxes[i * 4 + 3], 0.0f), H_IMG);
    g_bx1[r] = x1; g_by1[r] = y1; g_bx2[r] = x2; g_by2[r] = y2;
    g_s[r] = scores[i];
    g_xord[g_posx[i]] = r;
}

// ---------------------------------------------------------------------------
// K4: [R7 verbatim] warp per bin-sorted row a. Candidates: positions (a, end)
// where end = binOff[bin(x2_a + 2) + 1]; conservative superset, exact
// reference arithmetic decides. Edges in score-index space (i<j).
// ---------------------------------------------------------------------------
__global__ void k_edges() {
    int warp = (blockIdx.x * blockDim.x + threadIdx.x) >> 5;
    int lane = threadIdx.x & 31;
    if (warp >= NN) return;
    int a = warp;
    float4 A = g_xs4[a];
    int   pa = g_xord[a];
    float aa = __fmul_rn(__fadd_rn(__fsub_rn(A.z, A.x), 1.0f),
                         __fadd_rn(__fsub_rn(A.w, A.y), 1.0f));
    float thresh = A.z + 2.0f;
    int binMax = (int)(thresh * INV_BINW);
    if (binMax > BINS - 1) binMax = BINS - 1;
    int end = g_binOff[binMax + 1];

    for (int b0 = a + 1; b0 < end; b0 += 32) {
        int b = b0 + lane;
        if (b < end) {
            float4 B = g_xs4[b];
            if (B.x <= thresh) {
                float ix1 = fmaxf(A.x, B.x);
                float iy1 = fmaxf(A.y, B.y);
                float ix2 = fminf(A.z, B.z);
                float iy2 = fminf(A.w, B.w);
                float iw = fmaxf(__fadd_rn(__fsub_rn(ix2, ix1), 1.0f), 0.0f);
                float ih = fmaxf(__fadd_rn(__fsub_rn(iy2, iy1), 1.0f), 0.0f);
                float inter = __fmul_rn(iw, ih);
                if (inter > 0.0f) {
                    float ab = __fmul_rn(__fadd_rn(__fsub_rn(B.z, B.x), 1.0f),
                                         __fadd_rn(__fsub_rn(B.w, B.y), 1.0f));
                    float uni = __fsub_rn(__fadd_rn(aa, ab), inter);
                    if (__fdiv_rn(inter, uni) > 0.5f) {
                        int pb = g_xord[b];
                        int i = min(pa, pb);
                        int j = max(pa, pb);
                        int e = atomicAdd(&g_ecnt, 1);
                        if (e < ECAP) {
                            g_eh[e] = i;
                            g_ej[e] = j;
                            atomicAdd(&g_degIn[j], 1);
                        }
                    }
                }
            }
        }
    }
}

// ---------------------------------------------------------------------------
// K5: single-block tail. CSR scan+fill, then greedy-cluster fixpoint with
// REGISTER-CACHED neighbor lists (each thread owns 8 fixed nodes; rounds
// read only shared s_sc; degree>8 tail read from global — rare, exact).
// Then stats, first-pick, output.
// ---------------------------------------------------------------------------
__global__ void __launch_bounds__(1024)
k_post(const int* __restrict__ nmp, float* __restrict__ out, int out_size) {
    __shared__ short          s_sc[NN];      // -1 undecided / cluster id
    __shared__ unsigned short s_off[NN];     // CSR starts (total < 65536)
    __shared__ int            s_sums[1024];
    __shared__ int            s_total, s_ch;
    int tid = threadIdx.x;

    // (a) scan of g_degIn -> s_off (exclusive), s_total
    {
        int base = tid * 8;
        int ex[8];
        int sum = 0;
#pragma unroll
        for (int r = 0; r < 8; r++) {
            int v = g_degIn[base + r];
            ex[r] = sum;
            sum += v;
        }
        s_sums[tid] = sum;
        __syncthreads();
        for (int off = 1; off < 1024; off <<= 1) {
            int t = (tid >= off) ? s_sums[tid - off] : 0;
            __syncthreads();
            s_sums[tid] += t;
            __syncthreads();
        }
        int blockEx = s_sums[tid] - sum;
#pragma unroll
        for (int r = 0; r < 8; r++)
            s_off[base + r] = (unsigned short)(blockEx + ex[r]);
        if (tid == 1023) s_total = blockEx + sum;
    }
    __syncthreads();
    int total = s_total;

    // (b) CSR fill
    {
        int ec = g_ecnt;
        if (ec > ECAP) ec = ECAP;
        for (int e = tid; e < ec; e += 1024) {
            int j = g_ej[e];
            int pos = (int)s_off[j] + atomicAdd(&g_cursor[j], 1);
            g_inList[pos] = g_eh[e];
        }
    }
    __syncthreads();

    // (c) fixpoint with cached neighbors. Thread owns nodes i = r*1024+tid.
    short nbr[8][8];                 // cached in-neighbors (ids < 8192)
    unsigned char ndeg[8];           // full degree (may exceed 8)
    unsigned undecided = 0;          // bitmask over r

#pragma unroll
    for (int r = 0; r < 8; r++) {
        int i = r * 1024 + tid;
        int st = s_off[i];
        int en = (i < NN - 1) ? (int)s_off[i + 1] : total;
        int deg = en - st;
        ndeg[r] = (unsigned char)min(deg, 255);
        if (deg == 0) {
            s_sc[i] = (short)i;      // isolated -> head
        } else {
            s_sc[i] = -1;
            undecided |= (1u << r);
            int kmax = min(deg, 8);
            for (int k = 0; k < kmax; k++)
                nbr[r][k] = (short)g_inList[st + k];
        }
    }
    __syncthreads();

    for (int round = 0; round < 1024; round++) {
        if (tid == 0) s_ch = 0;
        __syncthreads();
        unsigned rem = undecided;
        while (rem) {
            int r = __ffs(rem) - 1;
            rem &= rem - 1;
            int i = r * 1024 + tid;
            int deg = ndeg[r];
            int m = 0x7fffffff, u = 0x7fffffff;
            int kmax = min(deg, 8);
            for (int k = 0; k < kmax; k++) {
                int h = nbr[r][k];
                int c = s_sc[h];
                if (c == h)      m = min(m, h);
                else if (c < 0)  u = min(u, h);
            }
            if (deg > 8) {           // rare overflow: exact tail from global
                int st = s_off[i];
                int en = (i < NN - 1) ? (int)s_off[i + 1] : total;
                for (int p = st + 8; p < en; p++) {
                    int h = g_inList[p];
                    int c = s_sc[h];
                    if (c == h)      m = min(m, h);
                    else if (c < 0)  u = min(u, h);
                }
            }
            if (m < u) {
                s_sc[i] = (short)m;
                undecided &= ~(1u << r);
                s_ch = 1;
            } else if (u == 0x7fffffff) {
                s_sc[i] = (short)i;
                undecided &= ~(1u << r);
                s_ch = 1;
            }
        }
        __syncthreads();
        int done = (s_ch == 0);
        __syncthreads();
        if (done) break;
    }

    // (d) stats
    for (int j = tid; j < NN; j += 1024) {
        int c = s_sc[j];
        atomicAdd(&g_count[c], 1);
        atomicAdd(&g_sum[c], g_s[j]);
        atomicMax(&g_maxY2[c], __float_as_uint(g_by2[j]));  // y2>=0 monotone
    }
    __syncthreads();

    // (e) first pick
    for (int j = tid; j < NN; j += 1024) {
        int c = s_sc[j];
        if (g_by2[j] >= __uint_as_float(g_maxY2[c])) atomicMin(&g_first[c], j);
    }
    __syncthreads();

    // (f) output: out[0..5N) = (N,5) rows, out[5N..6N) = keep as 0/1 floats.
    //     valid: counts >= nm/3  <=>  3*count >= nm (exact in ints)
    int nm = nmp[0];
    if (nm < 1 || nm > 1000000) {
        float f = __int_as_float(nm);
        nm = (int)f;
        if (nm < 1) nm = 1;
    }
    for (int j = tid; j < NN; j += 1024) {
        int c = s_sc[j];
        bool keep = (j == g_first[c]) && (3 * g_count[c] >= nm);
        float r0 = 0.f, r1 = 0.f, r2 = 0.f, r3 = 0.f, r4 = 0.f, kf = 0.f;
        if (keep) {
            r0 = g_bx1[j]; r1 = g_by1[j]; r2 = g_bx2[j]; r3 = g_by2[j];
            r4 = __fdiv_rn(g_sum[c], (float)nm);
            kf = 1.0f;
        }
        long long obase = (long long)j * 5;
        if (obase + 4 < out_size) {
            out[obase + 0] = r0; out[obase + 1] = r1; out[obase + 2] = r2;
            out[obase + 3] = r3; out[obase + 4] = r4;
        }
        long long kpos = (long long)NN * 5 + j;
        if (kpos < out_size) out[kpos] = kf;
    }
}

// ---------------------------------------------------------------------------
extern "C" void kernel_launch(void* const* d_in, const int* in_sizes, int n_in,
                              void* d_out, int out_size) {
    const float* boxes  = nullptr;
    const float* scores = nullptr;
    const int*   nmp    = nullptr;
    for (int k = 0; k < n_in; k++) {
        if (in_sizes[k] == NN * 4)      boxes  = (const float*)d_in[k];
        else if (in_sizes[k] == NN)     scores = (const float*)d_in[k];
        else if (in_sizes[k] == 1)      nmp    = (const int*)d_in[k];
    }
    if (!boxes)  boxes  = (const float*)d_in[0];
    if (!scores) scores = (const float*)d_in[1];
    if (!nmp)    nmp    = (const int*)d_in[n_in - 1];

    k_init<<<NN / 256, 256>>>(boxes, scores);
    k_scan<<<1, 1024>>>();
    k_scatter<<<NN / 256, 256>>>(boxes, scores);
    k_rankg<<<NN / 256, 256>>>(boxes, scores);
    k_edges<<<NN / 8, 256>>>();            // 8192 warps, warp per x-row
    k_post<<<1, 1024>>>(nmp, (float*)d_out, out_size);
}